// round 5
// baseline (speedup 1.0000x reference)
#include <cuda_runtime.h>

// Problem constants (fixed by the reference).
#define B_ROWS 16
#define D_LEN  2097152            // floats per row
#define D4_LEN (D_LEN / 4)        // float4 per row = 524288
#define BLOCKS_PER_ROW 64
#define CHUNK4 (D4_LEN / BLOCKS_PER_ROW)   // 8192 float4 per block
#define THREADS 256
#define TOTAL_BLOCKS (B_ROWS * BLOCKS_PER_ROW)  // 1024

// Deterministic scratch.
__device__ float g_partial[B_ROWS * BLOCKS_PER_ROW];  // per-(row, block) sumsq
__device__ float g_dist[B_ROWS];                      // per-row sqrt(sumsq)
__device__ unsigned int g_row_count[B_ROWS];          // row completion counters
__device__ unsigned int g_final_count;                // row-finalizer counter
// All counters start zero-initialized and are reset by their finalizers,
// so every graph replay sees identical initial state.

__global__ __launch_bounds__(THREADS)
void euclid_loss_kernel(const float4* __restrict__ out,
                        const float4* __restrict__ lab,
                        float* __restrict__ result) {
    const int row = blockIdx.y;
    const int blk = blockIdx.x;
    const size_t base = (size_t)row * D4_LEN + (size_t)blk * CHUNK4;

    float acc = 0.0f;
    // R1-proven streaming shape: 32 iterations, unroll 4 -> ptxas front-
    // batches 8 independent 16B loads per thread (high MLP).
    #pragma unroll 4
    for (int i = threadIdx.x; i < CHUNK4; i += THREADS) {
        float4 a = __ldg(&out[base + i]);
        float4 b = __ldg(&lab[base + i]);
        float dx = a.x - b.x;
        float dy = a.y - b.y;
        float dz = a.z - b.z;
        float dw = a.w - b.w;
        acc = fmaf(dx, dx, acc);
        acc = fmaf(dy, dy, acc);
        acc = fmaf(dz, dz, acc);
        acc = fmaf(dw, dw, acc);
    }

    // Block reduction: warp shuffle, then shared across 8 warps.
    __shared__ float s_warp[THREADS / 32];
    #pragma unroll
    for (int off = 16; off > 0; off >>= 1)
        acc += __shfl_xor_sync(0xFFFFFFFFu, acc, off);
    const int lane = threadIdx.x & 31;
    const int wid  = threadIdx.x >> 5;
    if (lane == 0) s_warp[wid] = acc;
    __syncthreads();

    // Thread 0 publishes the partial and checks row completion.
    __shared__ bool s_row_last;
    if (threadIdx.x == 0) {
        float v = 0.0f;
        #pragma unroll
        for (int w = 0; w < THREADS / 32; w++) v += s_warp[w];
        g_partial[row * BLOCKS_PER_ROW + blk] = v;
        __threadfence();
        unsigned int prev = atomicAdd(&g_row_count[row], 1u);
        s_row_last = (prev == BLOCKS_PER_ROW - 1);
    }
    __syncthreads();
    if (!s_row_last) return;

    // ---- Row finalizer: warp 0 reduces this row's 64 partials ----
    if (wid != 0) return;
    float v = __ldcg(&g_partial[row * BLOCKS_PER_ROW + lane])
            + __ldcg(&g_partial[row * BLOCKS_PER_ROW + 32 + lane]);
    #pragma unroll
    for (int off = 16; off > 0; off >>= 1)
        v += __shfl_xor_sync(0xFFFFFFFFu, v, off);

    bool final_last = false;
    if (lane == 0) {
        g_dist[row] = sqrtf(v);
        g_row_count[row] = 0;          // reset for next replay
        __threadfence();
        unsigned int prev = atomicAdd(&g_final_count, 1u);
        final_last = (prev == B_ROWS - 1);
    }
    if (!__shfl_sync(0xFFFFFFFFu, final_last ? 1 : 0, 0)) return;

    // ---- Global finalizer: mean of the 16 distances ----
    float d = (lane < B_ROWS) ? __ldcg(&g_dist[lane]) : 0.0f;
    #pragma unroll
    for (int off = 16; off > 0; off >>= 1)
        d += __shfl_xor_sync(0xFFFFFFFFu, d, off);
    if (lane == 0) {
        result[0] = d / (float)B_ROWS;
        g_final_count = 0;             // reset for next replay
    }
}

extern "C" void kernel_launch(void* const* d_in, const int* in_sizes, int n_in,
                              void* d_out, int out_size) {
    const float4* out = (const float4*)d_in[0];
    const float4* lab = (const float4*)d_in[1];
    float* res = (float*)d_out;

    dim3 grid(BLOCKS_PER_ROW, B_ROWS);
    euclid_loss_kernel<<<grid, THREADS>>>(out, lab, res);
}